// round 12
// baseline (speedup 1.0000x reference)
#include <cuda_runtime.h>
#include <cuda_bf16.h>

#define Bn 1024
#define Dn 512
#define On 256
#define BO (Bn * On)
#define DO (Dn * On)

// ---------------- device scratch (no allocations allowed) ----------------
__device__ float  g_SxP[8 * Dn];            // partial sums of (1-x) per 128-b chunk
__device__ float  g_rxpF[8 * DO];           // rel_x numerator partials [s][d][o]
__device__ float  g_relxT[On * Dn];         // rel_x transposed [o][d]
__device__ float  g_xT[Dn * Bn];            // x transposed [d][b]
__device__ float  g_tT[On * Bn];            // t transposed [o][b]

// =========================================================================
// k_front: 448 blocks
//   [0,256):   rel_x numerator partials (sum_b max(x,t)), 4x4 micro tiles
//   [256,384): Sx partials + x transpose
//   [384,448): t transpose
// =========================================================================
__global__ __launch_bounds__(256, 2) void k_front(const float* __restrict__ x,
                                                  const float* __restrict__ t) {
    __shared__ char smem[18048];
    int tid = threadIdx.x;
    int blk = blockIdx.x;

    if (blk < 256) {
        // ---------------- rel_x partials ----------------
        float (*xs)[68] = (float(*)[68])smem;           // [32][68]
        float (*ts)[68] = (float(*)[68])(smem + 8704);  // [32][68]
        int o0 = (blk & 3) * 64;
        int d0 = ((blk >> 2) & 7) * 64;
        int bs = blk >> 5;
        int tx = tid & 15;   // o quad
        int ty = tid >> 4;   // d quad
        double a[16];
#pragma unroll
        for (int k = 0; k < 16; k++) a[k] = 0.0;
        for (int chunk = 0; chunk < 4; chunk++) {
            int bc = bs * 128 + chunk * 32;
            __syncthreads();
            for (int u = tid; u < 512; u += 256) {
                int r = u >> 4, c = u & 15;
                *(float4*)&xs[r][c * 4] = *(const float4*)&x[(bc + r) * Dn + d0 + c * 4];
                *(float4*)&ts[r][c * 4] = *(const float4*)&t[(bc + r) * On + o0 + c * 4];
            }
            __syncthreads();
            float f[16];
#pragma unroll
            for (int k = 0; k < 16; k++) f[k] = 0.0f;
#pragma unroll
            for (int kb = 0; kb < 32; kb++) {
                float4 xv = *(const float4*)&xs[kb][ty * 4];
                float4 tv = *(const float4*)&ts[kb][tx * 4];
                f[0]  += fmaxf(xv.x, tv.x);  f[1]  += fmaxf(xv.x, tv.y);
                f[2]  += fmaxf(xv.x, tv.z);  f[3]  += fmaxf(xv.x, tv.w);
                f[4]  += fmaxf(xv.y, tv.x);  f[5]  += fmaxf(xv.y, tv.y);
                f[6]  += fmaxf(xv.y, tv.z);  f[7]  += fmaxf(xv.y, tv.w);
                f[8]  += fmaxf(xv.z, tv.x);  f[9]  += fmaxf(xv.z, tv.y);
                f[10] += fmaxf(xv.z, tv.z);  f[11] += fmaxf(xv.z, tv.w);
                f[12] += fmaxf(xv.w, tv.x);  f[13] += fmaxf(xv.w, tv.y);
                f[14] += fmaxf(xv.w, tv.z);  f[15] += fmaxf(xv.w, tv.w);
            }
#pragma unroll
            for (int k = 0; k < 16; k++) a[k] += (double)f[k];
        }
        float* p = g_rxpF + (size_t)bs * DO;
#pragma unroll
        for (int i = 0; i < 4; i++) {
            int d_ = d0 + ty * 4 + i;
            int o_ = o0 + tx * 4;
            float4 v4;
            v4.x = (float)a[i * 4 + 0];
            v4.y = (float)a[i * 4 + 1];
            v4.z = (float)a[i * 4 + 2];
            v4.w = (float)a[i * 4 + 3];
            *(float4*)&p[d_ * On + o_] = v4;
        }
    } else if (blk < 384) {
        // ---------------- Sx partials + x transpose ----------------
        float (*tile)[33] = (float(*)[33])smem;            // [128][33]
        float (*sh)[33]   = (float(*)[33])(smem + 16896);  // [8][33]
        int j = blk - 256;
        int d0 = (j & 15) * 32;
        int bs = j >> 4;
        int b0 = bs * 128;
#pragma unroll
        for (int p = 0; p < 16; p++) {
            int idx = p * 256 + tid;
            int row = idx >> 5, col = idx & 31;
            tile[row][col] = x[(b0 + row) * Dn + d0 + col];
        }
        __syncthreads();
        {
            int dt = tid & 31;
            int rt = tid >> 5;                // 0..7
            float s = 0.0f;
#pragma unroll
            for (int k = 0; k < 16; k++)
                s += 1.0f - tile[rt * 16 + k][dt];
            sh[rt][dt] = s;
            __syncthreads();
            if (rt == 0) {
                float acc = 0.0f;
#pragma unroll
                for (int r = 0; r < 8; r++) acc += sh[r][dt];
                g_SxP[bs * Dn + d0 + dt] = acc;
            }
        }
#pragma unroll
        for (int p = 0; p < 16; p++) {
            int idx = p * 256 + tid;
            int b = idx & 127, d = idx >> 7;
            g_xT[(d0 + d) * Bn + b0 + b] = tile[b][d];
        }
    } else {
        // ---------------- t transpose ----------------
        float (*tile)[33] = (float(*)[33])smem;  // [128][33]
        int j = blk - 384;                        // 0..63
        int o0 = (j & 7) * 32;
        int b0 = (j >> 3) * 128;
#pragma unroll
        for (int p = 0; p < 16; p++) {
            int idx = p * 256 + tid;
            int row = idx >> 5, col = idx & 31;
            tile[row][col] = t[(b0 + row) * On + o0 + col];
        }
        __syncthreads();
#pragma unroll
        for (int p = 0; p < 16; p++) {
            int idx = p * 256 + tid;
            int b = idx & 127, o = idx >> 7;
            g_tT[(o0 + o) * Bn + b0 + b] = tile[b][o];
        }
    }
}

// ---------------- combine rel_x partials (+Sx) + transpose to [o][d] -----
// one thread per element; fully coalesced partial reads
__global__ __launch_bounds__(256) void k_transRel() {
    int i = blockIdx.x * 256 + threadIdx.x;  // [d][o] linear
    int d = i >> 8;
    int o = i & 255;
    double a = 0.0;
#pragma unroll
    for (int s = 0; s < 8; s++) a += (double)g_rxpF[(size_t)s * DO + i];
    double sx = 0.0;
#pragma unroll
    for (int s = 0; s < 8; s++) sx += (double)g_SxP[s * Dn + d];  // broadcast
    g_relxT[o * Dn + d] = (float)(1.0 - ((double)Bn - a) / sx);
}

// ---------------- x-side: sort rel_x col, lockstep early-exit walk -------
// grid 256 (one block per o)
__global__ __launch_bounds__(256) void k_solveX(const float* __restrict__ w,
                                                float* __restrict__ out) {
    int o = blockIdx.x;
    int tid = threadIdx.x;
    __shared__ unsigned long long keys[Dn];
    for (int i = tid; i < Dn; i += 256) {
        unsigned int kb = __float_as_uint(g_relxT[o * Dn + i]);  // rel in [0,1]
        keys[i] = ((unsigned long long)kb << 32) | (unsigned int)i;
    }
    __syncthreads();
    // bitonic sort ascending on packed keys
    for (int k = 2; k <= Dn; k <<= 1) {
        for (int j = k >> 1; j > 0; j >>= 1) {
            for (int t2 = tid; t2 < Dn; t2 += 256) {
                int ixj = t2 ^ j;
                if (ixj > t2) {
                    bool up = ((t2 & k) == 0);
                    unsigned long long ka = keys[t2], kb2 = keys[ixj];
                    if ((ka > kb2) == up) { keys[t2] = kb2; keys[ixj] = ka; }
                }
            }
            __syncthreads();
        }
    }
    // lockstep chunked walk: argmin_d max(x[b,d], rel_x[d,o])
    for (int bb = 0; bb < 4; bb++) {
        int b = bb * 256 + tid;
        float bv = 3.4e38f;
        int bd = Dn;
        bool active = true;
        for (int k0 = 0; k0 < Dn; k0 += 8) {
            if (!__ballot_sync(0xFFFFFFFFu, active)) break;
            float rr[8], xv[8];
            int dd[8];
#pragma unroll
            for (int j = 0; j < 8; j++) {
                unsigned long long key = keys[k0 + j];
                rr[j] = __uint_as_float((unsigned int)(key >> 32));
                dd[j] = (int)(key & 0xFFFFFFFFu);
                xv[j] = g_xT[dd[j] * Bn + b];   // d uniform, b lane-consecutive
            }
#pragma unroll
            for (int j = 0; j < 8; j++) {
                if (active) {
                    if (rr[j] > bv) { active = false; }
                    else {
                        float v = fmaxf(xv[j], rr[j]);
                        if (v < bv || (v == bv && dd[j] < bd)) { bv = v; bd = dd[j]; }
                    }
                }
            }
        }
        out[b * On + o] = fmaxf(g_xT[bd * Bn + b], w[bd * On + o]);
    }
}

// ---------------- w-side: sort w col, scans, binary-search walk ----------
// grid 256 (one block per o)
__global__ __launch_bounds__(256) void k_solveW(const float* __restrict__ w,
                                                float* __restrict__ out) {
    int o = blockIdx.x;
    int tid = threadIdx.x;
    __shared__ float  sv[Dn];
    __shared__ float  ss[Dn];
    __shared__ float  pma[Dn];
    __shared__ float  pmb[Dn];
    __shared__ double sa[Dn];
    __shared__ double sb[Dn];
    for (int i = tid; i < Dn; i += 256) {
        float v = w[i * On + o];
        sv[i] = v;
        ss[i] = v;
    }
    __syncthreads();
    // bitonic sort ascending
    for (int k = 2; k <= Dn; k <<= 1) {
        for (int j = k >> 1; j > 0; j >>= 1) {
            for (int t2 = tid; t2 < Dn; t2 += 256) {
                int ixj = t2 ^ j;
                if (ixj > t2) {
                    bool up = ((t2 & k) == 0);
                    float a = ss[t2], b2 = ss[ixj];
                    if ((a > b2) == up) { ss[t2] = b2; ss[ixj] = a; }
                }
            }
            __syncthreads();
        }
    }
    // parallel prefix-min (original order) + suffix-sum (sorted, double)
    for (int i = tid; i < Dn; i += 256) {
        pma[i] = sv[i];
        sa[i] = (double)ss[i];
    }
    __syncthreads();
    bool ping = true;
    for (int off = 1; off < Dn; off <<= 1) {
        float*  psrc = ping ? pma : pmb;
        float*  pdst = ping ? pmb : pma;
        double* ssrc = ping ? sa : sb;
        double* sdst = ping ? sb : sa;
        for (int i = tid; i < Dn; i += 256) {
            pdst[i] = (i >= off) ? fminf(psrc[i], psrc[i - off]) : psrc[i];
            sdst[i] = (i + off < Dn) ? ssrc[i] + ssrc[i + off] : ssrc[i];
        }
        __syncthreads();
        ping = !ping;
    }
    float*  pm  = ping ? pma : pmb;
    double* suf = ping ? sa : sb;
    double Sw = (double)Dn - suf[0];
    float gm = pm[Dn - 1];
    for (int b = tid; b < Bn; b += 256) {
        float tv = g_tT[o * Bn + b];
        int lo = 0, hi = Dn;
        while (lo < hi) {
            int m = (lo + hi) >> 1;
            if (ss[m] <= tv) lo = m + 1; else hi = m;
        }
        int c = lo;
        double sufc = (c < Dn) ? suf[c] : 0.0;
        double N = (double)c * (double)tv + sufc;
        float thr = (float)(1.0 - ((double)Dn - N) / Sw);
        int ind;
        if (gm <= thr) {
            lo = 0; hi = Dn - 1;
            while (lo < hi) {
                int m = (lo + hi) >> 1;
                if (pm[m] <= thr) hi = m; else lo = m + 1;
            }
            ind = lo;
        } else {
            lo = 0; hi = Dn - 1;
            while (lo < hi) {
                int m = (lo + hi) >> 1;
                if (pm[m] <= gm) hi = m; else lo = m + 1;
            }
            ind = lo;
        }
        out[BO + b * On + o] = fmaxf(g_xT[ind * Bn + b], w[ind * On + o]);
    }
}

extern "C" void kernel_launch(void* const* d_in, const int* in_sizes, int n_in,
                              void* d_out, int out_size) {
    (void)in_sizes; (void)n_in; (void)out_size;
    const float* x = (const float*)d_in[0];
    const float* w = (const float*)d_in[1];
    const float* t = (const float*)d_in[2];
    float* out = (float*)d_out;

    k_front<<<448, 256>>>(x, t);
    k_transRel<<<DO / 256, 256>>>();
    k_solveX<<<On, 256>>>(w, out);
    k_solveW<<<On, 256>>>(w, out);
}

// round 14
// speedup vs baseline: 1.2613x; 1.2613x over previous
#include <cuda_runtime.h>
#include <cuda_bf16.h>

#define Bn 1024
#define Dn 512
#define On 256
#define BO (Bn * On)
#define DO (Dn * On)

// ---------------- device scratch (no allocations allowed) ----------------
__device__ float  g_SxP[8 * Dn];            // partial sums of (1-x) per 128-b chunk
__device__ float  g_rxpF[8 * DO];           // rel_x numerator partials [s][d][o]
__device__ float  g_relxT[On * Dn];         // rel_x transposed [o][d]
__device__ float  g_xT[Dn * Bn];            // x transposed [d][b]
__device__ float  g_tT[On * Bn];            // t transposed [o][b]

// =========================================================================
// k_front: 448 blocks
//   [0,256):   rel_x numerator partials (sum_b max(x,t)), 4x4 micro tiles
//   [256,384): Sx partials + x transpose
//   [384,448): t transpose
// =========================================================================
__global__ __launch_bounds__(256, 2) void k_front(const float* __restrict__ x,
                                                  const float* __restrict__ t) {
    __shared__ char smem[18048];
    int tid = threadIdx.x;
    int blk = blockIdx.x;

    if (blk < 256) {
        // ---------------- rel_x partials ----------------
        float (*xs)[68] = (float(*)[68])smem;           // [32][68]
        float (*ts)[68] = (float(*)[68])(smem + 8704);  // [32][68]
        int o0 = (blk & 3) * 64;
        int d0 = ((blk >> 2) & 7) * 64;
        int bs = blk >> 5;
        int tx = tid & 15;   // o quad
        int ty = tid >> 4;   // d quad
        double a[16];
#pragma unroll
        for (int k = 0; k < 16; k++) a[k] = 0.0;
        for (int chunk = 0; chunk < 4; chunk++) {
            int bc = bs * 128 + chunk * 32;
            __syncthreads();
            for (int u = tid; u < 512; u += 256) {
                int r = u >> 4, c = u & 15;
                *(float4*)&xs[r][c * 4] = *(const float4*)&x[(bc + r) * Dn + d0 + c * 4];
                *(float4*)&ts[r][c * 4] = *(const float4*)&t[(bc + r) * On + o0 + c * 4];
            }
            __syncthreads();
            float f[16];
#pragma unroll
            for (int k = 0; k < 16; k++) f[k] = 0.0f;
#pragma unroll
            for (int kb = 0; kb < 32; kb++) {
                float4 xv = *(const float4*)&xs[kb][ty * 4];
                float4 tv = *(const float4*)&ts[kb][tx * 4];
                f[0]  += fmaxf(xv.x, tv.x);  f[1]  += fmaxf(xv.x, tv.y);
                f[2]  += fmaxf(xv.x, tv.z);  f[3]  += fmaxf(xv.x, tv.w);
                f[4]  += fmaxf(xv.y, tv.x);  f[5]  += fmaxf(xv.y, tv.y);
                f[6]  += fmaxf(xv.y, tv.z);  f[7]  += fmaxf(xv.y, tv.w);
                f[8]  += fmaxf(xv.z, tv.x);  f[9]  += fmaxf(xv.z, tv.y);
                f[10] += fmaxf(xv.z, tv.z);  f[11] += fmaxf(xv.z, tv.w);
                f[12] += fmaxf(xv.w, tv.x);  f[13] += fmaxf(xv.w, tv.y);
                f[14] += fmaxf(xv.w, tv.z);  f[15] += fmaxf(xv.w, tv.w);
            }
#pragma unroll
            for (int k = 0; k < 16; k++) a[k] += (double)f[k];
        }
        float* p = g_rxpF + (size_t)bs * DO;
#pragma unroll
        for (int i = 0; i < 4; i++) {
            int d_ = d0 + ty * 4 + i;
            int o_ = o0 + tx * 4;
            float4 v4;
            v4.x = (float)a[i * 4 + 0];
            v4.y = (float)a[i * 4 + 1];
            v4.z = (float)a[i * 4 + 2];
            v4.w = (float)a[i * 4 + 3];
            *(float4*)&p[d_ * On + o_] = v4;
        }
    } else if (blk < 384) {
        // ---------------- Sx partials + x transpose ----------------
        float (*tile)[33] = (float(*)[33])smem;            // [128][33]
        float (*sh)[33]   = (float(*)[33])(smem + 16896);  // [8][33]
        int j = blk - 256;
        int d0 = (j & 15) * 32;
        int bs = j >> 4;
        int b0 = bs * 128;
#pragma unroll
        for (int p = 0; p < 16; p++) {
            int idx = p * 256 + tid;
            int row = idx >> 5, col = idx & 31;
            tile[row][col] = x[(b0 + row) * Dn + d0 + col];
        }
        __syncthreads();
        {
            int dt = tid & 31;
            int rt = tid >> 5;                // 0..7
            float s = 0.0f;
#pragma unroll
            for (int k = 0; k < 16; k++)
                s += 1.0f - tile[rt * 16 + k][dt];
            sh[rt][dt] = s;
            __syncthreads();
            if (rt == 0) {
                float acc = 0.0f;
#pragma unroll
                for (int r = 0; r < 8; r++) acc += sh[r][dt];
                g_SxP[bs * Dn + d0 + dt] = acc;
            }
        }
#pragma unroll
        for (int p = 0; p < 16; p++) {
            int idx = p * 256 + tid;
            int b = idx & 127, d = idx >> 7;
            g_xT[(d0 + d) * Bn + b0 + b] = tile[b][d];
        }
    } else {
        // ---------------- t transpose ----------------
        float (*tile)[33] = (float(*)[33])smem;  // [128][33]
        int j = blk - 384;                        // 0..63
        int o0 = (j & 7) * 32;
        int b0 = (j >> 3) * 128;
#pragma unroll
        for (int p = 0; p < 16; p++) {
            int idx = p * 256 + tid;
            int row = idx >> 5, col = idx & 31;
            tile[row][col] = t[(b0 + row) * On + o0 + col];
        }
        __syncthreads();
#pragma unroll
        for (int p = 0; p < 16; p++) {
            int idx = p * 256 + tid;
            int b = idx & 127, o = idx >> 7;
            g_tT[(o0 + o) * Bn + b0 + b] = tile[b][o];
        }
    }
}

// ---------------- combine rel_x partials (+Sx) + transpose to [o][d] -----
// one thread per element; fully coalesced partial reads
__global__ __launch_bounds__(256) void k_transRel() {
    int i = blockIdx.x * 256 + threadIdx.x;  // [d][o] linear
    int d = i >> 8;
    int o = i & 255;
    double a = 0.0;
#pragma unroll
    for (int s = 0; s < 8; s++) a += (double)g_rxpF[(size_t)s * DO + i];
    double sx = 0.0;
#pragma unroll
    for (int s = 0; s < 8; s++) sx += (double)g_SxP[s * Dn + d];  // broadcast
    g_relxT[o * Dn + d] = (float)(1.0 - ((double)Bn - a) / sx);
}

// ---------------- solve both sides: grid 512 (fused for co-scheduling) ---
// blocks [0,256): x-side  (sort rel_x col, lockstep early-exit argmin walk)
// blocks [256,512): w-side (sort w col, scans, binary-search walk)
__global__ __launch_bounds__(256) void k_solve(const float* __restrict__ w,
                                               float* __restrict__ out) {
    int o = blockIdx.x & 255;
    int tid = threadIdx.x;
    __shared__ unsigned long long keys[Dn];   // x-side sort keys
    __shared__ float  sv[Dn];
    __shared__ float  pma[Dn];
    __shared__ float  pmb[Dn];
    __shared__ double sa[Dn];
    __shared__ double sb[Dn];

    if (blockIdx.x < 256) {
        // ------------------ x-side ------------------
        for (int i = tid; i < Dn; i += 256) {
            unsigned int kb = __float_as_uint(g_relxT[o * Dn + i]);  // rel in [0,1]
            keys[i] = ((unsigned long long)kb << 32) | (unsigned int)i;
        }
        __syncthreads();
        // bitonic sort ascending on packed keys
        for (int k = 2; k <= Dn; k <<= 1) {
            for (int j = k >> 1; j > 0; j >>= 1) {
                for (int t2 = tid; t2 < Dn; t2 += 256) {
                    int ixj = t2 ^ j;
                    if (ixj > t2) {
                        bool up = ((t2 & k) == 0);
                        unsigned long long ka = keys[t2], kb2 = keys[ixj];
                        if ((ka > kb2) == up) { keys[t2] = kb2; keys[ixj] = ka; }
                    }
                }
                __syncthreads();
            }
        }
        // lockstep chunked walk: argmin_d max(x[b,d], rel_x[d,o])
        for (int bb = 0; bb < 4; bb++) {
            int b = bb * 256 + tid;
            float bv = 3.4e38f;
            int bd = Dn;
            bool active = true;
            for (int k0 = 0; k0 < Dn; k0 += 8) {
                if (!__ballot_sync(0xFFFFFFFFu, active)) break;
                float rr[8], xv[8];
                int dd[8];
#pragma unroll
                for (int j = 0; j < 8; j++) {
                    unsigned long long key = keys[k0 + j];
                    rr[j] = __uint_as_float((unsigned int)(key >> 32));
                    dd[j] = (int)(key & 0xFFFFFFFFu);
                    xv[j] = g_xT[dd[j] * Bn + b];   // d uniform, b lane-consecutive
                }
#pragma unroll
                for (int j = 0; j < 8; j++) {
                    if (active) {
                        if (rr[j] > bv) { active = false; }
                        else {
                            float v = fmaxf(xv[j], rr[j]);
                            if (v < bv || (v == bv && dd[j] < bd)) { bv = v; bd = dd[j]; }
                        }
                    }
                }
            }
            out[b * On + o] = fmaxf(g_xT[bd * Bn + b], w[bd * On + o]);
        }
    } else {
        // ------------------ w-side ------------------
        float* ss = (float*)keys;  // reuse (2KB of the 4KB)
        for (int i = tid; i < Dn; i += 256) {
            float v = w[i * On + o];
            sv[i] = v;
            ss[i] = v;
        }
        __syncthreads();
        // bitonic sort ascending
        for (int k = 2; k <= Dn; k <<= 1) {
            for (int j = k >> 1; j > 0; j >>= 1) {
                for (int t2 = tid; t2 < Dn; t2 += 256) {
                    int ixj = t2 ^ j;
                    if (ixj > t2) {
                        bool up = ((t2 & k) == 0);
                        float a = ss[t2], b2 = ss[ixj];
                        if ((a > b2) == up) { ss[t2] = b2; ss[ixj] = a; }
                    }
                }
                __syncthreads();
            }
        }
        // parallel prefix-min (original order) + suffix-sum (sorted, double)
        for (int i = tid; i < Dn; i += 256) {
            pma[i] = sv[i];
            sa[i] = (double)ss[i];
        }
        __syncthreads();
        bool ping = true;
        for (int off = 1; off < Dn; off <<= 1) {
            float*  psrc = ping ? pma : pmb;
            float*  pdst = ping ? pmb : pma;
            double* ssrc = ping ? sa : sb;
            double* sdst = ping ? sb : sa;
            for (int i = tid; i < Dn; i += 256) {
                pdst[i] = (i >= off) ? fminf(psrc[i], psrc[i - off]) : psrc[i];
                sdst[i] = (i + off < Dn) ? ssrc[i] + ssrc[i + off] : ssrc[i];
            }
            __syncthreads();
            ping = !ping;
        }
        float*  pm  = ping ? pma : pmb;
        double* suf = ping ? sa : sb;
        double Sw = (double)Dn - suf[0];
        float gm = pm[Dn - 1];
        for (int b = tid; b < Bn; b += 256) {
            float tv = g_tT[o * Bn + b];
            int lo = 0, hi = Dn;
            while (lo < hi) {
                int m = (lo + hi) >> 1;
                if (ss[m] <= tv) lo = m + 1; else hi = m;
            }
            int c = lo;
            double sufc = (c < Dn) ? suf[c] : 0.0;
            double N = (double)c * (double)tv + sufc;
            float thr = (float)(1.0 - ((double)Dn - N) / Sw);
            int ind;
            if (gm <= thr) {
                lo = 0; hi = Dn - 1;
                while (lo < hi) {
                    int m = (lo + hi) >> 1;
                    if (pm[m] <= thr) hi = m; else lo = m + 1;
                }
                ind = lo;
            } else {
                lo = 0; hi = Dn - 1;
                while (lo < hi) {
                    int m = (lo + hi) >> 1;
                    if (pm[m] <= gm) hi = m; else lo = m + 1;
                }
                ind = lo;
            }
            out[BO + b * On + o] = fmaxf(g_xT[ind * Bn + b], w[ind * On + o]);
        }
    }
}

extern "C" void kernel_launch(void* const* d_in, const int* in_sizes, int n_in,
                              void* d_out, int out_size) {
    (void)in_sizes; (void)n_in; (void)out_size;
    const float* x = (const float*)d_in[0];
    const float* w = (const float*)d_in[1];
    const float* t = (const float*)d_in[2];
    float* out = (float*)d_out;

    k_front<<<448, 256>>>(x, t);
    k_transRel<<<DO / 256, 256>>>();
    k_solve<<<512, 256>>>(w, out);
}